// round 13
// baseline (speedup 1.0000x reference)
#include <cuda_runtime.h>
#include <cstdint>

// SceneContraction — final matrix cell: TMA bulk load @ SPB=512 (best measured
// ncu kernel time, 55.4us in R5) + default-policy STG.128 stores (the store
// path shared by every wall-clock winner). One mbarrier, compute in place,
// one __syncthreads before stores.
// means = contract(mean); cov_out = J cov J (J symmetric) for ||x||>=1 else pass.
// J = g*I + c*x x^T, g=(2-1/m)/m, c=2(1-m)/m^4, m=||x||.

#define TPB         256
#define SPB         512
#define MEAN_F      (SPB * 3)            // 1536 floats
#define COV_F       (SPB * 9)            // 4608 floats
#define MEAN_B      (MEAN_F * 4)         // 6144 bytes
#define COV_B       (COV_F * 4)          // 18432 bytes
#define TILE_BYTES  (MEAN_B + COV_B)
#define M4          (MEAN_F / 4)         // 384 float4
#define C4          (COV_F / 4)          // 1152 float4

__device__ __forceinline__ uint32_t smem_u32(const void* p) {
    return (uint32_t)__cvta_generic_to_shared(p);
}

__device__ __forceinline__ void contract_one(
    float x0, float x1, float x2,
    float c00, float c01, float c02,
    float c10, float c11, float c12,
    float c20, float c21, float c22,
    float& r0, float& r1, float& r2,
    float& o00, float& o01, float& o02,
    float& o10, float& o11, float& o12,
    float& o20, float& o21, float& o22)
{
    float m2 = fmaf(x0, x0, fmaf(x1, x1, x2 * x2));
    float m  = sqrtf(m2);

    r0 = x0; r1 = x1; r2 = x2;
    o00 = c00; o01 = c01; o02 = c02;
    o10 = c10; o11 = c11; o12 = c12;
    o20 = c20; o21 = c21; o22 = c22;

    if (m >= 1.0f) {
        float inv  = 1.0f / m;
        float g    = (2.0f - inv) * inv;
        float inv2 = inv * inv;
        float cc   = 2.0f * (1.0f - m) * inv2 * inv2;

        r0 = g * x0; r1 = g * x1; r2 = g * x2;

        float J00 = fmaf(cc, x0 * x0, g);
        float J11 = fmaf(cc, x1 * x1, g);
        float J22 = fmaf(cc, x2 * x2, g);
        float J01 = cc * x0 * x1;
        float J02 = cc * x0 * x2;
        float J12 = cc * x1 * x2;

        float b00 = J00*c00 + J01*c10 + J02*c20;
        float b01 = J00*c01 + J01*c11 + J02*c21;
        float b02 = J00*c02 + J01*c12 + J02*c22;
        float b10 = J01*c00 + J11*c10 + J12*c20;
        float b11 = J01*c01 + J11*c11 + J12*c21;
        float b12 = J01*c02 + J11*c12 + J12*c22;
        float b20 = J02*c00 + J12*c10 + J22*c20;
        float b21 = J02*c01 + J12*c11 + J22*c21;
        float b22 = J02*c02 + J12*c12 + J22*c22;

        o00 = b00*J00 + b01*J01 + b02*J02;
        o01 = b00*J01 + b01*J11 + b02*J12;
        o02 = b00*J02 + b01*J12 + b02*J22;
        o10 = b10*J00 + b11*J01 + b12*J02;
        o11 = b10*J01 + b11*J11 + b12*J12;
        o12 = b10*J02 + b11*J12 + b12*J22;
        o20 = b20*J00 + b21*J01 + b22*J02;
        o21 = b20*J01 + b21*J11 + b22*J12;
        o22 = b20*J02 + b21*J12 + b22*J22;
    }
}

__global__ __launch_bounds__(TPB) void scene_contraction_kernel(
    const float* __restrict__ mean,   // [N,3]
    const float* __restrict__ cov,    // [N,3,3]
    float* __restrict__ out_mean,     // [N,3]
    float* __restrict__ out_cov,      // [N,3,3]
    int n)
{
    __shared__ alignas(128) float s_mean[MEAN_F];
    __shared__ alignas(128) float s_cov[COV_F];
    __shared__ alignas(8) unsigned long long s_mbar;

    const int t = threadIdx.x;
    const int base = blockIdx.x * SPB;

    if (base + SPB <= n) {
        const uint32_t mbar = smem_u32(&s_mbar);
        const uint32_t smn  = smem_u32(s_mean);
        const uint32_t scv  = smem_u32(s_cov);

        if (t == 0) {
            asm volatile("mbarrier.init.shared.b64 [%0], 1;" :: "r"(mbar) : "memory");
        }
        __syncthreads();

        if (t == 0) {
            const float* gm = mean + (size_t)blockIdx.x * MEAN_F;
            const float* gc = cov  + (size_t)blockIdx.x * COV_F;
            asm volatile("mbarrier.arrive.expect_tx.shared.b64 _, [%0], %1;"
                         :: "r"(mbar), "r"((uint32_t)TILE_BYTES) : "memory");
            asm volatile("cp.async.bulk.shared::cta.global.mbarrier::complete_tx::bytes "
                         "[%0], [%1], %2, [%3];"
                         :: "r"(scv), "l"(gc), "r"((uint32_t)COV_B), "r"(mbar) : "memory");
            asm volatile("cp.async.bulk.shared::cta.global.mbarrier::complete_tx::bytes "
                         "[%0], [%1], %2, [%3];"
                         :: "r"(smn), "l"(gm), "r"((uint32_t)MEAN_B), "r"(mbar) : "memory");
        }

        // all threads wait on the tile (phase 0)
        {
            uint32_t done;
            asm volatile(
                "{\n\t.reg .pred p;\n\t"
                "mbarrier.try_wait.parity.shared.b64 p, [%1], 0;\n\t"
                "selp.b32 %0, 1, 0, p;\n\t}"
                : "=r"(done) : "r"(mbar) : "memory");
            if (!done) {
                asm volatile(
                    "{\n\t.reg .pred P1;\n"
                    "WL_%=:\n\t"
                    "mbarrier.try_wait.parity.shared.b64 P1, [%0], 0;\n\t"
                    "@P1 bra.uni WD_%=;\n\t"
                    "bra.uni WL_%=;\n"
                    "WD_%=:\n\t}"
                    :: "r"(mbar) : "memory");
            }
        }

        // ---- compute 2 samples/thread, results in place (disjoint regions) ----
        #pragma unroll
        for (int s = 0; s < SPB / TPB; s++) {
            const int idx = t + s * TPB;
            float x0 = s_mean[3*idx+0], x1 = s_mean[3*idx+1], x2 = s_mean[3*idx+2];
            float c00 = s_cov[9*idx+0], c01 = s_cov[9*idx+1], c02 = s_cov[9*idx+2];
            float c10 = s_cov[9*idx+3], c11 = s_cov[9*idx+4], c12 = s_cov[9*idx+5];
            float c20 = s_cov[9*idx+6], c21 = s_cov[9*idx+7], c22 = s_cov[9*idx+8];

            float r0, r1, r2, o00, o01, o02, o10, o11, o12, o20, o21, o22;
            contract_one(x0, x1, x2, c00, c01, c02, c10, c11, c12, c20, c21, c22,
                         r0, r1, r2, o00, o01, o02, o10, o11, o12, o20, o21, o22);

            s_mean[3*idx+0] = r0;  s_mean[3*idx+1] = r1;  s_mean[3*idx+2] = r2;
            s_cov[9*idx+0] = o00;  s_cov[9*idx+1] = o01;  s_cov[9*idx+2] = o02;
            s_cov[9*idx+3] = o10;  s_cov[9*idx+4] = o11;  s_cov[9*idx+5] = o12;
            s_cov[9*idx+6] = o20;  s_cov[9*idx+7] = o21;  s_cov[9*idx+8] = o22;
        }
        __syncthreads();

        // ---- coalesced 128-bit default-policy stores from smem ----
        const float4* sm4 = reinterpret_cast<const float4*>(s_mean);
        const float4* sc4 = reinterpret_cast<const float4*>(s_cov);
        float4* om = reinterpret_cast<float4*>(out_mean) + (size_t)blockIdx.x * M4;
        float4* oc = reinterpret_cast<float4*>(out_cov)  + (size_t)blockIdx.x * C4;
        #pragma unroll
        for (int i = t; i < M4; i += TPB) om[i] = sm4[i];
        #pragma unroll
        for (int i = t; i < C4; i += TPB) oc[i] = sc4[i];
    } else {
        // ---- scalar tail path ----
        for (int s = 0; s < SPB / TPB; s++) {
            int i = base + t + s * TPB;
            if (i >= n) return;
            const float* xp = mean + 3ull * i;
            const float* cp = cov + 9ull * i;
            float r0, r1, r2, o00, o01, o02, o10, o11, o12, o20, o21, o22;
            contract_one(xp[0], xp[1], xp[2],
                         cp[0], cp[1], cp[2], cp[3], cp[4], cp[5], cp[6], cp[7], cp[8],
                         r0, r1, r2, o00, o01, o02, o10, o11, o12, o20, o21, o22);
            float* om = out_mean + 3ull * i;
            float* oc = out_cov  + 9ull * i;
            om[0]=r0; om[1]=r1; om[2]=r2;
            oc[0]=o00; oc[1]=o01; oc[2]=o02;
            oc[3]=o10; oc[4]=o11; oc[5]=o12;
            oc[6]=o20; oc[7]=o21; oc[8]=o22;
        }
    }
}

extern "C" void kernel_launch(void* const* d_in, const int* in_sizes, int n_in,
                              void* d_out, int out_size)
{
    const float* mean = (const float*)d_in[0];   // [N,3]
    const float* cov  = (const float*)d_in[1];   // [N,3,3]
    int n = in_sizes[0] / 3;

    float* out_mean = (float*)d_out;
    float* out_cov  = (float*)d_out + 3ull * n;

    int blocks = (n + SPB - 1) / SPB;
    scene_contraction_kernel<<<blocks, TPB>>>(mean, cov, out_mean, out_cov, n);
}

// round 14
// speedup vs baseline: 1.0361x; 1.0361x over previous
#include <cuda_runtime.h>

// SceneContraction — FINAL (champion config, R2 verbatim).
// Session summary: HBM-bound pointwise op, 402 MB irreducible 1:1 R/W traffic.
// R1 scalar-strided: 125us (L1tex wavefront-bound, 9 wavefronts/LDG).
// R2 smem-staged coalesced 128-bit I/O: 63.0us — the one structural 2x win.
// R3-R13 probed tile size, barriers, TMA ld/st, streaming hints, L2 residency
// policies (both directions), intra-CTA pipelines, persistent CTAs: all
// 63.2-64.3us. Steady-state wall is pinned by DVFS-limited sustained HBM rate
// (~6.3 TB/s for this mix); plain LDG + default-policy STG measured fastest.
// Math: means = contract(mean); cov_out = J cov J (J symmetric) for ||x||>=1,
// else passthrough. J = g*I + c*x x^T, g=(2-1/m)/m, c=2(1-m)/m^4, m=||x||.

#define TPB 256
#define M4 (TPB * 3 / 4)   // 192 float4 of mean per block
#define C4 (TPB * 9 / 4)   // 576 float4 of cov per block

__global__ __launch_bounds__(TPB) void scene_contraction_kernel(
    const float* __restrict__ mean,   // [N,3]
    const float* __restrict__ cov,    // [N,3,3]
    float* __restrict__ out_mean,     // [N,3]
    float* __restrict__ out_cov,      // [N,3,3]
    int n)
{
    __shared__ float4 s_mean4[M4];
    __shared__ float4 s_cov4[C4];
    float* s_mean = reinterpret_cast<float*>(s_mean4);
    float* s_cov  = reinterpret_cast<float*>(s_cov4);

    const int t = threadIdx.x;
    const int base = blockIdx.x * TPB;   // first sample of this block

    if (base + TPB <= n) {
        // ---- coalesced load into smem ----
        const float4* gm = reinterpret_cast<const float4*>(mean) + (size_t)blockIdx.x * M4;
        const float4* gc = reinterpret_cast<const float4*>(cov)  + (size_t)blockIdx.x * C4;
        if (t < M4) s_mean4[t] = gm[t];
        #pragma unroll
        for (int i = t; i < C4; i += TPB) s_cov4[i] = gc[i];
        __syncthreads();

        // ---- per-sample compute from smem (stride 3 / 9: bank-conflict-free) ----
        float x0 = s_mean[3*t+0], x1 = s_mean[3*t+1], x2 = s_mean[3*t+2];
        float c00 = s_cov[9*t+0], c01 = s_cov[9*t+1], c02 = s_cov[9*t+2];
        float c10 = s_cov[9*t+3], c11 = s_cov[9*t+4], c12 = s_cov[9*t+5];
        float c20 = s_cov[9*t+6], c21 = s_cov[9*t+7], c22 = s_cov[9*t+8];

        float m2 = fmaf(x0, x0, fmaf(x1, x1, x2 * x2));
        float m  = sqrtf(m2);

        float r0 = x0, r1 = x1, r2 = x2;
        float o00 = c00, o01 = c01, o02 = c02;
        float o10 = c10, o11 = c11, o12 = c12;
        float o20 = c20, o21 = c21, o22 = c22;

        if (m >= 1.0f) {
            float inv  = 1.0f / m;
            float g    = (2.0f - inv) * inv;
            float inv2 = inv * inv;
            float cc   = 2.0f * (1.0f - m) * inv2 * inv2;

            r0 = g * x0; r1 = g * x1; r2 = g * x2;

            float J00 = fmaf(cc, x0 * x0, g);
            float J11 = fmaf(cc, x1 * x1, g);
            float J22 = fmaf(cc, x2 * x2, g);
            float J01 = cc * x0 * x1;
            float J02 = cc * x0 * x2;
            float J12 = cc * x1 * x2;

            float b00 = J00*c00 + J01*c10 + J02*c20;
            float b01 = J00*c01 + J01*c11 + J02*c21;
            float b02 = J00*c02 + J01*c12 + J02*c22;
            float b10 = J01*c00 + J11*c10 + J12*c20;
            float b11 = J01*c01 + J11*c11 + J12*c21;
            float b12 = J01*c02 + J11*c12 + J12*c22;
            float b20 = J02*c00 + J12*c10 + J22*c20;
            float b21 = J02*c01 + J12*c11 + J22*c21;
            float b22 = J02*c02 + J12*c12 + J22*c22;

            o00 = b00*J00 + b01*J01 + b02*J02;
            o01 = b00*J01 + b01*J11 + b02*J12;
            o02 = b00*J02 + b01*J12 + b02*J22;
            o10 = b10*J00 + b11*J01 + b12*J02;
            o11 = b10*J01 + b11*J11 + b12*J12;
            o12 = b10*J02 + b11*J12 + b12*J22;
            o20 = b20*J00 + b21*J01 + b22*J02;
            o21 = b20*J01 + b21*J11 + b22*J12;
            o22 = b20*J02 + b21*J12 + b22*J22;
        }

        __syncthreads();   // everyone done reading smem

        s_mean[3*t+0] = r0; s_mean[3*t+1] = r1; s_mean[3*t+2] = r2;
        s_cov[9*t+0] = o00; s_cov[9*t+1] = o01; s_cov[9*t+2] = o02;
        s_cov[9*t+3] = o10; s_cov[9*t+4] = o11; s_cov[9*t+5] = o12;
        s_cov[9*t+6] = o20; s_cov[9*t+7] = o21; s_cov[9*t+8] = o22;
        __syncthreads();

        // ---- coalesced store from smem ----
        float4* om = reinterpret_cast<float4*>(out_mean) + (size_t)blockIdx.x * M4;
        float4* oc = reinterpret_cast<float4*>(out_cov)  + (size_t)blockIdx.x * C4;
        if (t < M4) om[t] = s_mean4[t];
        #pragma unroll
        for (int i = t; i < C4; i += TPB) oc[i] = s_cov4[i];
    } else {
        // ---- scalar tail path ----
        int i = base + t;
        if (i >= n) return;
        const float* xp = mean + 3ull * i;
        float x0 = xp[0], x1 = xp[1], x2 = xp[2];
        const float* cp = cov + 9ull * i;
        float c00 = cp[0], c01 = cp[1], c02 = cp[2];
        float c10 = cp[3], c11 = cp[4], c12 = cp[5];
        float c20 = cp[6], c21 = cp[7], c22 = cp[8];

        float m2 = fmaf(x0, x0, fmaf(x1, x1, x2 * x2));
        float m  = sqrtf(m2);
        float* om = out_mean + 3ull * i;
        float* oc = out_cov  + 9ull * i;
        if (m < 1.0f) {
            om[0]=x0; om[1]=x1; om[2]=x2;
            oc[0]=c00; oc[1]=c01; oc[2]=c02;
            oc[3]=c10; oc[4]=c11; oc[5]=c12;
            oc[6]=c20; oc[7]=c21; oc[8]=c22;
        } else {
            float inv  = 1.0f / m;
            float g    = (2.0f - inv) * inv;
            float inv2 = inv * inv;
            float cc   = 2.0f * (1.0f - m) * inv2 * inv2;
            om[0] = g*x0; om[1] = g*x1; om[2] = g*x2;
            float J00 = fmaf(cc, x0*x0, g);
            float J11 = fmaf(cc, x1*x1, g);
            float J22 = fmaf(cc, x2*x2, g);
            float J01 = cc*x0*x1, J02 = cc*x0*x2, J12 = cc*x1*x2;
            float b00 = J00*c00 + J01*c10 + J02*c20;
            float b01 = J00*c01 + J01*c11 + J02*c21;
            float b02 = J00*c02 + J01*c12 + J02*c22;
            float b10 = J01*c00 + J11*c10 + J12*c20;
            float b11 = J01*c01 + J11*c11 + J12*c21;
            float b12 = J01*c02 + J11*c12 + J12*c22;
            float b20 = J02*c00 + J12*c10 + J22*c20;
            float b21 = J02*c01 + J12*c11 + J22*c21;
            float b22 = J02*c02 + J12*c12 + J22*c22;
            oc[0] = b00*J00 + b01*J01 + b02*J02;
            oc[1] = b00*J01 + b01*J11 + b02*J12;
            oc[2] = b00*J02 + b01*J12 + b02*J22;
            oc[3] = b10*J00 + b11*J01 + b12*J02;
            oc[4] = b10*J01 + b11*J11 + b12*J12;
            oc[5] = b10*J02 + b11*J12 + b12*J22;
            oc[6] = b20*J00 + b21*J01 + b22*J02;
            oc[7] = b20*J01 + b21*J11 + b22*J12;
            oc[8] = b20*J02 + b21*J12 + b22*J22;
        }
    }
}

extern "C" void kernel_launch(void* const* d_in, const int* in_sizes, int n_in,
                              void* d_out, int out_size)
{
    const float* mean = (const float*)d_in[0];   // [N,3]
    const float* cov  = (const float*)d_in[1];   // [N,3,3]
    int n = in_sizes[0] / 3;

    float* out_mean = (float*)d_out;
    float* out_cov  = (float*)d_out + 3ull * n;

    int blocks = (n + TPB - 1) / TPB;
    scene_contraction_kernel<<<blocks, TPB>>>(mean, cov, out_mean, out_cov, n);
}